// round 13
// baseline (speedup 1.0000x reference)
#include <cuda_runtime.h>
#include <cuda_bf16.h>
#include <cstdint>

// LSTM decoder: B=1024, H=128, O=7, T=512.
// gates = h @ (W_ih+W_hh)^T + (b_ih+b_hh)
// Grid = 148 blocks (one per SM): 136 x 7 rows + 12 x 6 rows. TPB=128.
// Thread t owns unit u=t, all 4 gates, all NR rows. fp32x2 packed FMA.
// o-gate streamed from L2 with depth-8 ring prefetch; pred GEMM for step s-1
// runs in the prologue-LDG latency shadow. One sync per step.
// Elementwise uses fused sigmoid*tanh reciprocals (8 MUFU/row instead of 10).
// k4=0 weights persist in registers across all steps.

#define B_TOTAL   1024
#define HID       128
#define GATES     512
#define T_STEPS   512
#define OUT_DIM   7
#define RMAX      7
#define NBLOCKS   148
#define NB7       136               // blocks with 7 rows (136*7 + 12*6 = 1024)
#define TPB       128

__device__ float4 g_W[32 * GATES];   // [k4][g] combined transposed weights, 256 KB
__device__ float  g_bias[GATES];

// ---------- helpers ----------
__device__ __forceinline__ void ffma2(unsigned long long& d,
                                      unsigned long long a,
                                      unsigned long long b) {
    asm("fma.rn.f32x2 %0, %1, %2, %0;" : "+l"(d) : "l"(a), "l"(b));
}
__device__ __forceinline__ unsigned long long pack_bias(float b) {
    unsigned long long v;
    asm("mov.b64 %0, {%1, %2};" : "=l"(v) : "f"(b), "f"(0.0f));
    return v;
}
__device__ __forceinline__ float pairsum(unsigned long long v) {
    float a, b;
    asm("mov.b64 {%0, %1}, %2;" : "=f"(a), "=f"(b) : "l"(v));
    return a + b;
}
__device__ __forceinline__ float sigf(float x) {
    return __fdividef(1.0f, 1.0f + __expf(-x));
}
// sig(a)*tanh(b) = (1 - e^{-2b}) / ((1 + e^{-a}) (1 + e^{-2b}))  : 2 EX2 + 1 RCP
__device__ __forceinline__ float sig_mul_tanh(float a, float b) {
    float ea = __expf(-a);
    float eb = __expf(-2.0f * b);
    return __fdividef(1.0f - eb, (1.0f + ea) * (1.0f + eb));
}

// ---------- prep ----------
__global__ void prep_kernel(const float* __restrict__ Wih,
                            const float* __restrict__ Whh,
                            const float* __restrict__ bih,
                            const float* __restrict__ bhh) {
    int idx = blockIdx.x * blockDim.x + threadIdx.x;
    if (idx < 32 * GATES) {
        int g  = idx & (GATES - 1);
        int k4 = idx >> 9;
        int base = g * HID + k4 * 4;
        float4 v;
        v.x = Wih[base + 0] + Whh[base + 0];
        v.y = Wih[base + 1] + Whh[base + 1];
        v.z = Wih[base + 2] + Whh[base + 2];
        v.w = Wih[base + 3] + Whh[base + 3];
        g_W[k4 * GATES + g] = v;
    }
    if (idx < GATES) g_bias[idx] = bih[idx] + bhh[idx];
}

// ---------- SMEM layout (floats) ----------
#define SW_F4       (32 * 384)                     // 12288 float4 : gates i,f,g (192 KB)
#define SH_OFF_F    (SW_F4 * 4)                    // 49152 : h double buffer 2*RMAX*128
#define SWOUT_OFF_F (SH_OFF_F + 2 * RMAX * HID)    // 49152 + 1792 = 50944
#define SMEM_BYTES  ((SWOUT_OFF_F + OUT_DIM * 33 * 4) * 4)   // 207472

template<int NR>
__device__ __forceinline__ void lstm_body(const float* __restrict__ ctx,
                                          const float* __restrict__ Wout,
                                          const float* __restrict__ bout,
                                          float* __restrict__ out,
                                          int row_base) {
    extern __shared__ float smem[];
    float4* s_w    = reinterpret_cast<float4*>(smem);
    float*  s_h    = smem + SH_OFF_F;
    float4* s_wout = reinterpret_cast<float4*>(smem + SWOUT_OFF_F);

    const int t = threadIdx.x;   // hidden unit

    // stage W (i,f,g) into shared
    for (int i = t; i < SW_F4; i += TPB) {
        int k4 = i / 384;
        int g  = i - k4 * 384;
        s_w[i] = g_W[k4 * GATES + g];
    }
    // stage W_out (padded pitch 33)
    const float4* Wout4 = reinterpret_cast<const float4*>(Wout);
    for (int i = t; i < OUT_DIM * 32; i += TPB) {
        int o = i / 32, kk = i - o * 32;
        s_wout[o * 33 + kk] = Wout4[o * 32 + kk];
    }
    // h0 = ctx[b][255][:]
#pragma unroll
    for (int r = 0; r < NR; r++) {
        int b = row_base + r;
        s_h[r * HID + t] = ctx[((size_t)b * 256 + 255) * HID + t];
    }

    // biases of unit t's 4 gates, packed for accumulator init
    const unsigned long long bi = pack_bias(g_bias[t]);
    const unsigned long long bf = pack_bias(g_bias[HID + t]);
    const unsigned long long bg = pack_bias(g_bias[2 * HID + t]);
    const unsigned long long bo = pack_bias(g_bias[3 * HID + t]);

    // o-gate L2 stream base (row pitch GATES ulonglong2 per k4)
    const ulonglong2* __restrict__ wO =
        reinterpret_cast<const ulonglong2*>(&g_W[3 * HID + t]);

    // pred mapping: thread groups of 16 -> one row each, 7 active lanes
    const int pr = t >> 4;          // row 0..7
    const int po = t & 15;          // out idx, active if < 7
    const bool do_pred = (po < OUT_DIM) && (pr < NR);
    const float bpred = do_pred ? bout[po] : 0.0f;
    float* out_base = out + ((size_t)(row_base + pr) * T_STEPS) * OUT_DIM + po;

    float c[NR];
#pragma unroll
    for (int r = 0; r < NR; r++) c[r] = 0.0f;

    __syncthreads();

    // k4=0 weights persist in registers for the whole kernel (values static)
    const ulonglong2 w0p = *reinterpret_cast<const ulonglong2*>(&s_w[t]);
    const ulonglong2 w1p = *reinterpret_cast<const ulonglong2*>(&s_w[HID + t]);
    const ulonglong2 w2p = *reinterpret_cast<const ulonglong2*>(&s_w[2 * HID + t]);

    int cur = 0;
    for (int s = 0; s < T_STEPS; s++) {
        const float* hc = s_h + cur * (RMAX * HID);
        float*       hn = s_h + (cur ^ 1) * (RMAX * HID);

        // ---- issue deep o-gate prefetch FIRST (8 LDGs in flight) ----
        ulonglong2 w3buf[8];
#pragma unroll
        for (int j = 0; j < 8; j++) w3buf[j] = __ldg(&wO[(size_t)j * GATES]);

        // ---- pred for step s-1 in the LDG latency shadow (hc = h_new of s-1) ----
        if (s > 0 && do_pred) {
            const float4* hr = reinterpret_cast<const float4*>(hc + pr * HID);
            const float4* wr = s_wout + po * 33;
            float pa = 0.0f;
#pragma unroll 8
            for (int kk = 0; kk < 32; kk++) {
                float4 hv = hr[kk];
                float4 wv = wr[kk];
                pa += hv.x * wv.x + hv.y * wv.y + hv.z * wv.z + hv.w * wv.w;
            }
            out_base[(size_t)(s - 1) * OUT_DIM] = pa + bpred;
        }

        unsigned long long a0[NR], a1[NR], a2[NR], a3[NR];
#pragma unroll
        for (int r = 0; r < NR; r++) { a0[r] = bi; a1[r] = bf; a2[r] = bg; a3[r] = bo; }

#pragma unroll 8
        for (int k4 = 0; k4 < 32; k4++) {
            ulonglong2 w0, w1, w2;
            if (k4 == 0) { w0 = w0p; w1 = w1p; w2 = w2p; }
            else {
                w0 = *reinterpret_cast<const ulonglong2*>(&s_w[k4 * 384 + t]);
                w1 = *reinterpret_cast<const ulonglong2*>(&s_w[k4 * 384 + HID + t]);
                w2 = *reinterpret_cast<const ulonglong2*>(&s_w[k4 * 384 + 2 * HID + t]);
            }
            ulonglong2 w3 = w3buf[k4 & 7];
            if (k4 + 8 < 32)
                w3buf[k4 & 7] = __ldg(&wO[(size_t)(k4 + 8) * GATES]);   // distance-8 refill
#pragma unroll
            for (int r = 0; r < NR; r++) {
                ulonglong2 h2 = *reinterpret_cast<const ulonglong2*>(hc + r * HID + k4 * 4); // bcast
                ffma2(a0[r], h2.x, w0.x); ffma2(a0[r], h2.y, w0.y);
                ffma2(a1[r], h2.x, w1.x); ffma2(a1[r], h2.y, w1.y);
                ffma2(a2[r], h2.x, w2.x); ffma2(a2[r], h2.y, w2.y);
                ffma2(a3[r], h2.x, w3.x); ffma2(a3[r], h2.y, w3.y);
            }
        }

        // LSTM elementwise — fully thread-local (NR rows), 8 MUFU per row
#pragma unroll
        for (int r = 0; r < NR; r++) {
            float gi = pairsum(a0[r]);
            float gf = pairsum(a1[r]);
            float gg = pairsum(a2[r]);
            float go = pairsum(a3[r]);
            float fv = sigf(gf);
            float ig = sig_mul_tanh(gi, gg);     // sig(i)*tanh(g): 2 EX2 + 1 RCP
            c[r] = fv * c[r] + ig;
            hn[r * HID + t] = sig_mul_tanh(go, c[r]);   // sig(o)*tanh(c)
        }
        __syncthreads();
        cur ^= 1;
    }

    // epilogue: pred for the final step (h_new lives in buffer `cur`)
    if (do_pred) {
        const float* hl = s_h + cur * (RMAX * HID);
        const float4* hr = reinterpret_cast<const float4*>(hl + pr * HID);
        const float4* wr = s_wout + po * 33;
        float pa = 0.0f;
#pragma unroll 8
        for (int kk = 0; kk < 32; kk++) {
            float4 hv = hr[kk];
            float4 wv = wr[kk];
            pa += hv.x * wv.x + hv.y * wv.y + hv.z * wv.z + hv.w * wv.w;
        }
        out_base[(size_t)(T_STEPS - 1) * OUT_DIM] = pa + bpred;
    }
}

__global__ void __launch_bounds__(TPB, 1)
lstm_kernel(const float* __restrict__ ctx,
            const float* __restrict__ Wout,
            const float* __restrict__ bout,
            float* __restrict__ out) {
    const int blk = blockIdx.x;
    if (blk < NB7) {
        lstm_body<7>(ctx, Wout, bout, out, blk * 7);
    } else {
        lstm_body<6>(ctx, Wout, bout, out, NB7 * 7 + (blk - NB7) * 6);
    }
}

extern "C" void kernel_launch(void* const* d_in, const int* in_sizes, int n_in,
                              void* d_out, int out_size) {
    const float* ctx  = (const float*)d_in[0];
    const float* Wih  = (const float*)d_in[1];
    const float* Whh  = (const float*)d_in[2];
    const float* bih  = (const float*)d_in[3];
    const float* bhh  = (const float*)d_in[4];
    const float* Wout = (const float*)d_in[5];
    const float* bout = (const float*)d_in[6];
    float* out = (float*)d_out;

    cudaFuncSetAttribute(lstm_kernel, cudaFuncAttributeMaxDynamicSharedMemorySize, SMEM_BYTES);

    prep_kernel<<<64, 256>>>(Wih, Whh, bih, bhh);
    lstm_kernel<<<NBLOCKS, TPB, SMEM_BYTES>>>(ctx, Wout, bout, out);
}

// round 14
// speedup vs baseline: 1.0354x; 1.0354x over previous
#include <cuda_runtime.h>
#include <cuda_bf16.h>
#include <cstdint>

// LSTM decoder: B=1024, H=128, O=7, T=512.
// gates = h @ (W_ih+W_hh)^T + (b_ih+b_hh)
// Grid = 148 blocks (one per SM): 136 x 7 rows + 12 x 6 rows. TPB=128.
// Thread t owns unit u=t, all 4 gates, all NR rows. fp32x2 packed FMA.
// o-gate streamed from L2 with depth-8 ring prefetch; pred GEMM for step s-1
// runs in the prologue-LDG latency shadow. One sync per step.
// Elementwise uses fused sigmoid*tanh reciprocals (8 MUFU/row instead of 10).
// (R12 base + MUFU fusion ONLY; k4=0 register hoist reverted — it regressed.)

#define B_TOTAL   1024
#define HID       128
#define GATES     512
#define T_STEPS   512
#define OUT_DIM   7
#define RMAX      7
#define NBLOCKS   148
#define NB7       136               // blocks with 7 rows (136*7 + 12*6 = 1024)
#define TPB       128

__device__ float4 g_W[32 * GATES];   // [k4][g] combined transposed weights, 256 KB
__device__ float  g_bias[GATES];

// ---------- helpers ----------
__device__ __forceinline__ void ffma2(unsigned long long& d,
                                      unsigned long long a,
                                      unsigned long long b) {
    asm("fma.rn.f32x2 %0, %1, %2, %0;" : "+l"(d) : "l"(a), "l"(b));
}
__device__ __forceinline__ unsigned long long pack_bias(float b) {
    unsigned long long v;
    asm("mov.b64 %0, {%1, %2};" : "=l"(v) : "f"(b), "f"(0.0f));
    return v;
}
__device__ __forceinline__ float pairsum(unsigned long long v) {
    float a, b;
    asm("mov.b64 {%0, %1}, %2;" : "=f"(a), "=f"(b) : "l"(v));
    return a + b;
}
__device__ __forceinline__ float sigf(float x) {
    return __fdividef(1.0f, 1.0f + __expf(-x));
}
// sig(a)*tanh(b) = (1 - e^{-2b}) / ((1 + e^{-a}) (1 + e^{-2b}))  : 2 EX2 + 1 RCP
__device__ __forceinline__ float sig_mul_tanh(float a, float b) {
    float ea = __expf(-a);
    float eb = __expf(-2.0f * b);
    return __fdividef(1.0f - eb, (1.0f + ea) * (1.0f + eb));
}

// ---------- prep ----------
__global__ void prep_kernel(const float* __restrict__ Wih,
                            const float* __restrict__ Whh,
                            const float* __restrict__ bih,
                            const float* __restrict__ bhh) {
    int idx = blockIdx.x * blockDim.x + threadIdx.x;
    if (idx < 32 * GATES) {
        int g  = idx & (GATES - 1);
        int k4 = idx >> 9;
        int base = g * HID + k4 * 4;
        float4 v;
        v.x = Wih[base + 0] + Whh[base + 0];
        v.y = Wih[base + 1] + Whh[base + 1];
        v.z = Wih[base + 2] + Whh[base + 2];
        v.w = Wih[base + 3] + Whh[base + 3];
        g_W[k4 * GATES + g] = v;
    }
    if (idx < GATES) g_bias[idx] = bih[idx] + bhh[idx];
}

// ---------- SMEM layout (floats) ----------
#define SW_F4       (32 * 384)                     // 12288 float4 : gates i,f,g (192 KB)
#define SH_OFF_F    (SW_F4 * 4)                    // 49152 : h double buffer 2*RMAX*128
#define SWOUT_OFF_F (SH_OFF_F + 2 * RMAX * HID)    // 49152 + 1792 = 50944
#define SMEM_BYTES  ((SWOUT_OFF_F + OUT_DIM * 33 * 4) * 4)   // 207472

template<int NR>
__device__ __forceinline__ void lstm_body(const float* __restrict__ ctx,
                                          const float* __restrict__ Wout,
                                          const float* __restrict__ bout,
                                          float* __restrict__ out,
                                          int row_base) {
    extern __shared__ float smem[];
    float4* s_w    = reinterpret_cast<float4*>(smem);
    float*  s_h    = smem + SH_OFF_F;
    float4* s_wout = reinterpret_cast<float4*>(smem + SWOUT_OFF_F);

    const int t = threadIdx.x;   // hidden unit

    // stage W (i,f,g) into shared
    for (int i = t; i < SW_F4; i += TPB) {
        int k4 = i / 384;
        int g  = i - k4 * 384;
        s_w[i] = g_W[k4 * GATES + g];
    }
    // stage W_out (padded pitch 33)
    const float4* Wout4 = reinterpret_cast<const float4*>(Wout);
    for (int i = t; i < OUT_DIM * 32; i += TPB) {
        int o = i / 32, kk = i - o * 32;
        s_wout[o * 33 + kk] = Wout4[o * 32 + kk];
    }
    // h0 = ctx[b][255][:]
#pragma unroll
    for (int r = 0; r < NR; r++) {
        int b = row_base + r;
        s_h[r * HID + t] = ctx[((size_t)b * 256 + 255) * HID + t];
    }

    // biases of unit t's 4 gates, packed for accumulator init
    const unsigned long long bi = pack_bias(g_bias[t]);
    const unsigned long long bf = pack_bias(g_bias[HID + t]);
    const unsigned long long bg = pack_bias(g_bias[2 * HID + t]);
    const unsigned long long bo = pack_bias(g_bias[3 * HID + t]);

    // o-gate L2 stream base (row pitch GATES ulonglong2 per k4)
    const ulonglong2* __restrict__ wO =
        reinterpret_cast<const ulonglong2*>(&g_W[3 * HID + t]);

    // pred mapping: thread groups of 16 -> one row each, 7 active lanes
    const int pr = t >> 4;          // row 0..7
    const int po = t & 15;          // out idx, active if < 7
    const bool do_pred = (po < OUT_DIM) && (pr < NR);
    const float bpred = do_pred ? bout[po] : 0.0f;
    float* out_base = out + ((size_t)(row_base + pr) * T_STEPS) * OUT_DIM + po;

    float c[NR];
#pragma unroll
    for (int r = 0; r < NR; r++) c[r] = 0.0f;

    __syncthreads();

    int cur = 0;
    for (int s = 0; s < T_STEPS; s++) {
        const float* hc = s_h + cur * (RMAX * HID);
        float*       hn = s_h + (cur ^ 1) * (RMAX * HID);

        // ---- issue deep o-gate prefetch FIRST (8 LDGs in flight) ----
        ulonglong2 w3buf[8];
#pragma unroll
        for (int j = 0; j < 8; j++) w3buf[j] = __ldg(&wO[(size_t)j * GATES]);

        // ---- pred for step s-1 in the LDG latency shadow (hc = h_new of s-1) ----
        if (s > 0 && do_pred) {
            const float4* hr = reinterpret_cast<const float4*>(hc + pr * HID);
            const float4* wr = s_wout + po * 33;
            float pa = 0.0f;
#pragma unroll 8
            for (int kk = 0; kk < 32; kk++) {
                float4 hv = hr[kk];
                float4 wv = wr[kk];
                pa += hv.x * wv.x + hv.y * wv.y + hv.z * wv.z + hv.w * wv.w;
            }
            out_base[(size_t)(s - 1) * OUT_DIM] = pa + bpred;
        }

        unsigned long long a0[NR], a1[NR], a2[NR], a3[NR];
#pragma unroll
        for (int r = 0; r < NR; r++) { a0[r] = bi; a1[r] = bf; a2[r] = bg; a3[r] = bo; }

#pragma unroll 8
        for (int k4 = 0; k4 < 32; k4++) {
            ulonglong2 w0 = *reinterpret_cast<const ulonglong2*>(&s_w[k4 * 384 + t]);
            ulonglong2 w1 = *reinterpret_cast<const ulonglong2*>(&s_w[k4 * 384 + HID + t]);
            ulonglong2 w2 = *reinterpret_cast<const ulonglong2*>(&s_w[k4 * 384 + 2 * HID + t]);
            ulonglong2 w3 = w3buf[k4 & 7];
            if (k4 + 8 < 32)
                w3buf[k4 & 7] = __ldg(&wO[(size_t)(k4 + 8) * GATES]);   // distance-8 refill
#pragma unroll
            for (int r = 0; r < NR; r++) {
                ulonglong2 h2 = *reinterpret_cast<const ulonglong2*>(hc + r * HID + k4 * 4); // bcast
                ffma2(a0[r], h2.x, w0.x); ffma2(a0[r], h2.y, w0.y);
                ffma2(a1[r], h2.x, w1.x); ffma2(a1[r], h2.y, w1.y);
                ffma2(a2[r], h2.x, w2.x); ffma2(a2[r], h2.y, w2.y);
                ffma2(a3[r], h2.x, w3.x); ffma2(a3[r], h2.y, w3.y);
            }
        }

        // LSTM elementwise — fully thread-local (NR rows), 8 MUFU per row
#pragma unroll
        for (int r = 0; r < NR; r++) {
            float gi = pairsum(a0[r]);
            float gf = pairsum(a1[r]);
            float gg = pairsum(a2[r]);
            float go = pairsum(a3[r]);
            float fv = sigf(gf);
            float ig = sig_mul_tanh(gi, gg);          // sig(i)*tanh(g): 2 EX2 + 1 RCP
            c[r] = fv * c[r] + ig;
            hn[r * HID + t] = sig_mul_tanh(go, c[r]); // sig(o)*tanh(c): 2 EX2 + 1 RCP
        }
        __syncthreads();
        cur ^= 1;
    }

    // epilogue: pred for the final step (h_new lives in buffer `cur`)
    if (do_pred) {
        const float* hl = s_h + cur * (RMAX * HID);
        const float4* hr = reinterpret_cast<const float4*>(hl + pr * HID);
        const float4* wr = s_wout + po * 33;
        float pa = 0.0f;
#pragma unroll 8
        for (int kk = 0; kk < 32; kk++) {
            float4 hv = hr[kk];
            float4 wv = wr[kk];
            pa += hv.x * wv.x + hv.y * wv.y + hv.z * wv.z + hv.w * wv.w;
        }
        out_base[(size_t)(T_STEPS - 1) * OUT_DIM] = pa + bpred;
    }
}

__global__ void __launch_bounds__(TPB, 1)
lstm_kernel(const float* __restrict__ ctx,
            const float* __restrict__ Wout,
            const float* __restrict__ bout,
            float* __restrict__ out) {
    const int blk = blockIdx.x;
    if (blk < NB7) {
        lstm_body<7>(ctx, Wout, bout, out, blk * 7);
    } else {
        lstm_body<6>(ctx, Wout, bout, out, NB7 * 7 + (blk - NB7) * 6);
    }
}

extern "C" void kernel_launch(void* const* d_in, const int* in_sizes, int n_in,
                              void* d_out, int out_size) {
    const float* ctx  = (const float*)d_in[0];
    const float* Wih  = (const float*)d_in[1];
    const float* Whh  = (const float*)d_in[2];
    const float* bih  = (const float*)d_in[3];
    const float* bhh  = (const float*)d_in[4];
    const float* Wout = (const float*)d_in[5];
    const float* bout = (const float*)d_in[6];
    float* out = (float*)d_out;

    cudaFuncSetAttribute(lstm_kernel, cudaFuncAttributeMaxDynamicSharedMemorySize, SMEM_BYTES);

    prep_kernel<<<64, 256>>>(Wih, Whh, bih, bhh);
    lstm_kernel<<<NBLOCKS, TPB, SMEM_BYTES>>>(ctx, Wout, bout, out);
}